// round 11
// baseline (speedup 1.0000x reference)
#include <cuda_runtime.h>

// ResidualDenseBlock: hybrid table + exact fixup.
// F (the composed 64-layer map) is O(1)-Lipschitz but has thin high-curvature
// "creases" (R9: bicubic ~= bilinear error => sub-cell features). Strategy:
//   K0: reset worklist counter;
//   K1: exact table at 1025^2 nodes;  K2: exact eval at 1024^2 cell centers,
//   flag cells where measured bilinear error > tol;  K2b: dilate flags 3x3;
//   K3: bilerp all rows, append rows in flagged cells to a worklist;
//   K4: exact 64-layer recompute for worklist rows.

#define LAYERS  64
#define GRID_N  1024
#define NODES   (GRID_N + 1)
#define DOM     6.0f
#define HSTEP   0.01171875f          // 12/1024 exact
#define INVH    85.33333333333333f   // 1024/12
#define UOFF    512.0f               // DOM*INVH exact
#define MAXROWS 4194304
#define FLAG_TOL 2.0e-4f

__device__ float2        g_tab[NODES * NODES];      // 8.4 MB
__device__ unsigned char g_flagA[GRID_N * GRID_N];  // 1 MB
__device__ unsigned char g_flagB[GRID_N * GRID_N];  // 1 MB
__device__ int           g_list[MAXROWS];           // 16.8 MB
__device__ int           g_count;

__device__ __forceinline__ float tanh_f32(float x) {
    float y;
    asm("tanh.approx.f32 %0, %1;" : "=f"(y) : "f"(x));
    return y;
}

__device__ __forceinline__ void load_params(const float* W, const float* b,
                                            const float* masks, const float* gates,
                                            float4* sW, float4* sB, float* sG)
{
    const int tid = threadIdx.x;
    if (tid < LAYERS) {
        sW[tid] = make_float4(W[tid*4+0], W[tid*4+1], W[tid*4+2], W[tid*4+3]);
        sB[tid] = make_float4(b[tid*2+0], b[tid*2+1], masks[tid], 0.0f);
    }
    if (tid == 0) {
        float s = 0.0f;
        #pragma unroll
        for (int i = 0; i < LAYERS; i++) s += gates[i];
        *sG = s;
    }
    __syncthreads();
}

__device__ __forceinline__ float2 scan64(float X, float Y,
                                         const float4* sW, const float4* sB)
{
    #pragma unroll 8
    for (int l = 0; l < LAYERS; l++) {
        const float4 w = sW[l];
        const float4 p = sB[l];
        float a0 = fmaf(w.x, X, fmaf(w.y, Y, p.x));
        float a1 = fmaf(w.z, X, fmaf(w.w, Y, p.y));
        X = fmaf(p.z, tanh_f32(a0), X);
        Y = fmaf(p.z, tanh_f32(a1), Y);
    }
    return make_float2(X, Y);
}

// ---------------- K0: reset worklist counter ----------------
__global__ void reset_count() { g_count = 0; }

// ---------------- K1: node table ----------------
__global__ __launch_bounds__(256)
void build_tab(const float* __restrict__ W, const float* __restrict__ b,
               const float* __restrict__ masks, const float* __restrict__ gates)
{
    __shared__ float4 sW[LAYERS]; __shared__ float4 sB[LAYERS]; __shared__ float sG;
    load_params(W, b, masks, gates, sW, sB, &sG);

    const int idx = blockIdx.x * 256 + threadIdx.x;
    if (idx >= NODES * NODES) return;
    const int iy = idx / NODES;
    const int ix = idx - iy * NODES;

    float2 r = scan64(fmaf((float)ix, HSTEP, -DOM),
                      fmaf((float)iy, HSTEP, -DOM), sW, sB);
    g_tab[idx] = make_float2(r.x * sG, r.y * sG);
}

// ---------------- K2: center test -> flags ----------------
__global__ __launch_bounds__(256)
void center_flag(const float* __restrict__ W, const float* __restrict__ b,
                 const float* __restrict__ masks, const float* __restrict__ gates)
{
    __shared__ float4 sW[LAYERS]; __shared__ float4 sB[LAYERS]; __shared__ float sG;
    load_params(W, b, masks, gates, sW, sB, &sG);

    const int idx = blockIdx.x * 256 + threadIdx.x;
    if (idx >= GRID_N * GRID_N) return;
    const int iy = idx / GRID_N;
    const int ix = idx - iy * GRID_N;

    float2 r = scan64(fmaf((float)ix + 0.5f, HSTEP, -DOM),
                      fmaf((float)iy + 0.5f, HSTEP, -DOM), sW, sB);
    float fx = r.x * sG, fy = r.y * sG;

    const float2* p = &g_tab[iy * NODES + ix];
    float2 f00 = p[0], f10 = p[1], f01 = p[NODES], f11 = p[NODES + 1];
    float bx = 0.25f * (f00.x + f10.x + f01.x + f11.x);
    float by = 0.25f * (f00.y + f10.y + f01.y + f11.y);

    float err   = fabsf(fx - bx) + fabsf(fy - by);
    float scale = fabsf(fx) + fabsf(fy) + 2.0f;
    g_flagA[idx] = (err > FLAG_TOL * scale) ? 1 : 0;
}

// ---------------- K2b: 3x3 dilation ----------------
__global__ __launch_bounds__(256)
void dilate_flags()
{
    const int idx = blockIdx.x * 256 + threadIdx.x;
    if (idx >= GRID_N * GRID_N) return;
    const int iy = idx / GRID_N;
    const int ix = idx - iy * GRID_N;

    unsigned char f = 0;
    #pragma unroll
    for (int dy = -1; dy <= 1; dy++) {
        int y = min(max(iy + dy, 0), GRID_N - 1);
        #pragma unroll
        for (int dx = -1; dx <= 1; dx++) {
            int x = min(max(ix + dx, 0), GRID_N - 1);
            f |= g_flagA[y * GRID_N + x];
        }
    }
    g_flagB[idx] = f;
}

// ---------------- K3: bilerp + compact flagged rows ----------------
__global__ __launch_bounds__(256)
void interp_kernel(const float2* __restrict__ x, float2* __restrict__ out,
                   int nrows)
{
    const int t = blockIdx.x * 256 + threadIdx.x;
    const bool active = (t < nrows);
    const int lane = threadIdx.x & 31;

    float X = 0.0f, Y = 0.0f;
    if (active) { float2 v = x[t]; X = v.x; Y = v.y; }

    float u = fminf(fmaxf(fmaf(X, INVH, UOFF), 0.0f), 1023.999f);
    float v = fminf(fmaxf(fmaf(Y, INVH, UOFF), 0.0f), 1023.999f);
    int ix = (int)u, iy = (int)v;
    float tx = u - (float)ix, ty = v - (float)iy;

    bool flagged = false;
    if (active)
        flagged = (g_flagB[iy * GRID_N + ix] != 0) ||
                  (fabsf(X) > 5.8f) || (fabsf(Y) > 5.8f);

    if (active) {
        const float2* p = &g_tab[iy * NODES + ix];
        float2 f00 = __ldg(p), f10 = __ldg(p + 1);
        float2 f01 = __ldg(p + NODES), f11 = __ldg(p + NODES + 1);
        float ax = fmaf(tx, f10.x - f00.x, f00.x);
        float bx = fmaf(tx, f11.x - f01.x, f01.x);
        float ay = fmaf(tx, f10.y - f00.y, f00.y);
        float by = fmaf(tx, f11.y - f01.y, f01.y);
        out[t] = make_float2(fmaf(ty, bx - ax, ax), fmaf(ty, by - ay, ay));
    }

    unsigned mask = __ballot_sync(0xffffffffu, flagged);
    if (flagged) {
        int leader = __ffs(mask) - 1;
        int base = 0;
        if (lane == leader) base = atomicAdd(&g_count, __popc(mask));
        base = __shfl_sync(mask, base, leader);
        int off = __popc(mask & ((1u << lane) - 1u));
        g_list[base + off] = t;
    }
}

// ---------------- K4: exact fixup for flagged rows ----------------
__global__ __launch_bounds__(256)
void fixup_kernel(const float2* __restrict__ x, float2* __restrict__ out,
                  const float* __restrict__ W, const float* __restrict__ b,
                  const float* __restrict__ masks, const float* __restrict__ gates)
{
    __shared__ float4 sW[LAYERS]; __shared__ float4 sB[LAYERS]; __shared__ float sG;
    load_params(W, b, masks, gates, sW, sB, &sG);

    const int n = g_count;
    const int stride = gridDim.x * 256;
    for (int i = blockIdx.x * 256 + threadIdx.x; i < n; i += stride) {
        int row = __ldg(&g_list[i]);
        float2 v = __ldg(&x[row]);
        float2 r = scan64(v.x, v.y, sW, sB);
        out[row] = make_float2(r.x * sG, r.y * sG);
    }
}

extern "C" void kernel_launch(void* const* d_in, const int* in_sizes, int n_in,
                              void* d_out, int out_size)
{
    const float* x     = (const float*)d_in[0];
    const float* W     = (const float*)d_in[1];
    const float* b     = (const float*)d_in[2];
    const float* masks = (const float*)d_in[3];
    const float* gates = (const float*)d_in[4];

    const int nrows = in_sizes[0] / 2;

    reset_count <<<1, 1>>>();
    build_tab   <<<(NODES*NODES + 255)/256, 256>>>(W, b, masks, gates);
    center_flag <<<(GRID_N*GRID_N + 255)/256, 256>>>(W, b, masks, gates);
    dilate_flags<<<(GRID_N*GRID_N + 255)/256, 256>>>();
    interp_kernel<<<(nrows + 255)/256, 256>>>((const float2*)x, (float2*)d_out, nrows);
    fixup_kernel<<<1024, 256>>>((const float2*)x, (float2*)d_out, W, b, masks, gates);
}

// round 13
// speedup vs baseline: 1.2350x; 1.2350x over previous
#include <cuda_runtime.h>

// ResidualDenseBlock: out = scan_{l=0..63}( tanh(out @ W[l]^T + b[l]) * m[l] + out ) * sum(gates)
//
// R12b: MUFU offload via shared-memory piecewise-linear tanh.
// All direct variants were XU-bound at ~64 cyc/layer/warp (8 tanh @ rt8; f16x2
// tanh is half-rate => no help). Rows 0,1 keep exact tanh.approx.f32 (4 MUFU);
// rows 2,3 use a 4096-entry log-indexed slope/intercept LUT in shared memory
// (LSU/ALU pipes, zero MUFU). XU drops to 32 cyc/layer; binder becomes issue.

#define LAYERS 64
#define TPB    256
#define TAB_N  4096          // 8 exp bits + 4 mantissa bits
#define GRID_BLOCKS 888      // 148 SMs * 6 blocks (36.5KB smem each)

typedef unsigned long long u64;

__device__ __forceinline__ float tanh_f32(float x) {
    float y;
    asm("tanh.approx.f32 %0, %1;" : "=f"(y) : "f"(x));
    return y;
}
__device__ __forceinline__ u64 fma2(u64 a, u64 b, u64 c) {
    u64 d;
    asm("fma.rn.f32x2 %0, %1, %2, %3;" : "=l"(d) : "l"(a), "l"(b), "l"(c));
    return d;
}
__device__ __forceinline__ u64 mul2(u64 a, u64 b) {
    u64 d;
    asm("mul.rn.f32x2 %0, %1, %2;" : "=l"(d) : "l"(a), "l"(b));
    return d;
}
__device__ __forceinline__ u64 pk2(float lo, float hi) {
    u64 d;
    asm("mov.b64 %0, {%1, %2};" : "=l"(d) : "f"(lo), "f"(hi));
    return d;
}
__device__ __forceinline__ void up2(float& lo, float& hi, u64 s) {
    asm("mov.b64 {%0, %1}, %2;" : "=f"(lo), "=f"(hi) : "l"(s));
}

struct __align__(16) LayerP {
    u64 w00, w01, w10, w11, b0, b1, m, pad;  // broadcast (v,v) f32x2 pairs
};

// log-indexed PWL tanh: index = {exp[7:0], mant[22:19]}, sign via xor on intercept.
__device__ __forceinline__ float lut_tanh(float v, const float2* tab) {
    unsigned bi = __float_as_uint(v);
    unsigned off = (bi >> 16) & 0x7FF8u;     // (exp:8|mant:4) * 8 bytes, sign stripped
    float2 sc = *reinterpret_cast<const float2*>(
        reinterpret_cast<const char*>(tab) + off);
    unsigned cs = __float_as_uint(sc.y) ^ (bi & 0x80000000u);
    return fmaf(sc.x, v, __uint_as_float(cs));
}

__global__ __launch_bounds__(TPB)
void rdb_kernel(const float4* __restrict__ x,
                const float*  __restrict__ W,
                const float*  __restrict__ b,
                const float*  __restrict__ masks,
                const float*  __restrict__ gates,
                float4* __restrict__ out,
                long long n4)                 // number of float4 = BATCH/2
{
    __shared__ float2 tab[TAB_N];            // 32 KB
    __shared__ LayerP sP[LAYERS];            // 4 KB
    __shared__ float  sG;

    const int tid = threadIdx.x;

    // ---- build PWL table ----
    // idx 1824 = exp 114 => x = 2^-13 (tanh(x)=x to 6e-13)
    // idx 2096 = exp 131 => x = 16    (tanh(x)=1  to 1e-14)
    for (int i = tid; i < TAB_N; i += TPB) {
        float s, c;
        if (i < 1824)       { s = 1.0f; c = 0.0f; }
        else if (i >= 2096) { s = 0.0f; c = 1.0f; }
        else {
            float x_lo = __uint_as_float((unsigned)i << 19);
            float x_hi = __uint_as_float((unsigned)(i + 1) << 19);
            float t_lo = tanh_f32(x_lo);
            float t_hi = tanh_f32(x_hi);
            s = (t_hi - t_lo) * __frcp_rn(x_hi - x_lo);
            c = fmaf(-s, x_lo, t_lo);
        }
        tab[i] = make_float2(s, c);
    }

    // ---- layer params ----
    if (tid < LAYERS) {
        float w00 = W[tid*4+0], w01 = W[tid*4+1];
        float w10 = W[tid*4+2], w11 = W[tid*4+3];
        float b0 = b[tid*2+0], b1 = b[tid*2+1];
        float m = masks[tid];
        LayerP p;
        p.w00 = pk2(w00, w00); p.w01 = pk2(w01, w01);
        p.w10 = pk2(w10, w10); p.w11 = pk2(w11, w11);
        p.b0  = pk2(b0, b0);   p.b1  = pk2(b1, b1);
        p.m   = pk2(m, m);     p.pad = 0;
        sP[tid] = p;
    }
    if (tid == 0) {
        float s = 0.0f;
        #pragma unroll
        for (int i = 0; i < LAYERS; i++) s += gates[i];
        sG = s;
    }
    __syncthreads();

    const float g = sG;
    const u64 g2 = pk2(g, g);
    const long long ngroups = (n4 + 1) / 2;          // 4-row groups
    const long long stride = (long long)gridDim.x * TPB;

    for (long long grp = (long long)blockIdx.x * TPB + tid;
         grp < ngroups; grp += stride) {

        const long long f4base = grp * 2;
        const bool have2 = (f4base + 1) < n4;

        float4 A = x[f4base];
        float4 C = have2 ? x[f4base + 1] : make_float4(0,0,0,0);

        u64 Xa = pk2(A.x, A.z), Ya = pk2(A.y, A.w);   // rows 0,1: MUFU tanh
        u64 Xc = pk2(C.x, C.z), Yc = pk2(C.y, C.w);   // rows 2,3: LUT tanh

        #pragma unroll 4
        for (int l = 0; l < LAYERS; l++) {
            const LayerP p = sP[l];

            u64 argA0 = fma2(p.w00, Xa, fma2(p.w01, Ya, p.b0));
            u64 argA1 = fma2(p.w10, Xa, fma2(p.w11, Ya, p.b1));
            u64 argC0 = fma2(p.w00, Xc, fma2(p.w01, Yc, p.b0));
            u64 argC1 = fma2(p.w10, Xc, fma2(p.w11, Yc, p.b1));

            float a0, a1, b0f, b1f, c0, c1, c2, c3;
            up2(a0, a1, argA0);
            up2(b0f, b1f, argA1);
            up2(c0, c2, argC0);
            up2(c1, c3, argC1);

            float t0 = tanh_f32(a0);
            float t1 = tanh_f32(a1);
            float t2 = tanh_f32(b0f);
            float t3 = tanh_f32(b1f);

            float u0 = lut_tanh(c0, tab);
            float u1 = lut_tanh(c1, tab);
            float u2 = lut_tanh(c2, tab);
            float u3 = lut_tanh(c3, tab);

            Xa = fma2(p.m, pk2(t0, t1), Xa);
            Ya = fma2(p.m, pk2(t2, t3), Ya);
            Xc = fma2(p.m, pk2(u0, u2), Xc);
            Yc = fma2(p.m, pk2(u1, u3), Yc);
        }

        u64 Ra = mul2(g2, Xa), Rb = mul2(g2, Ya);
        u64 Rc = mul2(g2, Xc), Rd = mul2(g2, Yc);

        float x0, x1, y0, y1;
        up2(x0, x1, Ra); up2(y0, y1, Rb);
        out[f4base] = make_float4(x0, y0, x1, y1);
        if (have2) {
            up2(x0, x1, Rc); up2(y0, y1, Rd);
            out[f4base + 1] = make_float4(x0, y0, x1, y1);
        }
    }
}

extern "C" void kernel_launch(void* const* d_in, const int* in_sizes, int n_in,
                              void* d_out, int out_size)
{
    const float4* x     = (const float4*)d_in[0];
    const float*  W     = (const float*) d_in[1];
    const float*  b     = (const float*) d_in[2];
    const float*  masks = (const float*) d_in[3];
    const float*  gates = (const float*) d_in[4];
    float4* out = (float4*)d_out;

    const long long nfloat = (long long)in_sizes[0];   // BATCH * 2
    const long long n4 = nfloat / 4;                   // BATCH / 2

    rdb_kernel<<<GRID_BLOCKS, TPB>>>(x, W, b, masks, gates, out, n4);
}

// round 14
// speedup vs baseline: 1.9541x; 1.5822x over previous
#include <cuda_runtime.h>

// ResidualDenseBlock: out = scan_{l=0..63}( tanh(out @ W[l]^T + b[l]) * m[l] + out ) * sum(gates)
//
// FINAL (== R4, best measured 133.2us): MUFU-roofline kernel.
// Evidence across R3-R13: XU cost is 64 cyc/layer/warp for ANY f32/f16x2 tanh mix
// (f16x2 tanh is half-rate); smem-LUT offload is crossbar-bound at >= MUFU cost;
// table/hybrid approaches fail on sub-cell curvature. This configuration
// (4 rows f32 tanh + 2x f16x2 tanh + packed f32x2 FMA + cvt unpack) measured
// fastest; every perturbation regressed.

#define LAYERS  64
#define TPB     256

typedef unsigned long long u64;

__device__ __forceinline__ float tanh_f32(float x) {
    float y;
    asm("tanh.approx.f32 %0, %1;" : "=f"(y) : "f"(x));
    return y;
}
__device__ __forceinline__ unsigned tanh_h2(unsigned h) {
    unsigned r;
    asm("tanh.approx.f16x2 %0, %1;" : "=r"(r) : "r"(h));
    return r;
}
// d = { hi = cvt(a), lo = cvt(b) }
__device__ __forceinline__ unsigned pack_h2(float hi, float lo) {
    unsigned r;
    asm("cvt.rn.f16x2.f32 %0, %1, %2;" : "=r"(r) : "f"(hi), "f"(lo));
    return r;
}
__device__ __forceinline__ void unpack_h2(float& lo, float& hi, unsigned h) {
    asm("{.reg .b16 l, u;\n\t"
        " mov.b32 {l, u}, %2;\n\t"
        " cvt.f32.f16 %0, l;\n\t"
        " cvt.f32.f16 %1, u;}"
        : "=f"(lo), "=f"(hi) : "r"(h));
}
__device__ __forceinline__ u64 fma2(u64 a, u64 b, u64 c) {
    u64 d;
    asm("fma.rn.f32x2 %0, %1, %2, %3;" : "=l"(d) : "l"(a), "l"(b), "l"(c));
    return d;
}
__device__ __forceinline__ u64 mul2(u64 a, u64 b) {
    u64 d;
    asm("mul.rn.f32x2 %0, %1, %2;" : "=l"(d) : "l"(a), "l"(b));
    return d;
}
__device__ __forceinline__ u64 pk2(float lo, float hi) {
    u64 d;
    asm("mov.b64 %0, {%1, %2};" : "=l"(d) : "f"(lo), "f"(hi));
    return d;
}
__device__ __forceinline__ void up2(float& lo, float& hi, u64 s) {
    asm("mov.b64 {%0, %1}, %2;" : "=f"(lo), "=f"(hi) : "l"(s));
}

struct __align__(16) LayerP {
    u64 w00, w01, w10, w11, b0, b1, m, pad;   // each holds (v, v) broadcast pair
};

__global__ __launch_bounds__(TPB)
void rdb_kernel(const float4* __restrict__ x,
                const float*  __restrict__ W,
                const float*  __restrict__ b,
                const float*  __restrict__ masks,
                const float*  __restrict__ gates,
                float4* __restrict__ out,
                long long nfloat4)
{
    __shared__ LayerP sP[LAYERS];
    __shared__ float  sG;

    const int tid = threadIdx.x;
    if (tid < LAYERS) {
        float w00 = W[tid * 4 + 0], w01 = W[tid * 4 + 1];
        float w10 = W[tid * 4 + 2], w11 = W[tid * 4 + 3];
        float b0 = b[tid * 2 + 0], b1 = b[tid * 2 + 1];
        float m = masks[tid];
        LayerP p;
        p.w00 = pk2(w00, w00); p.w01 = pk2(w01, w01);
        p.w10 = pk2(w10, w10); p.w11 = pk2(w11, w11);
        p.b0  = pk2(b0, b0);   p.b1  = pk2(b1, b1);
        p.m   = pk2(m, m);     p.pad = 0;
        sP[tid] = p;
    }
    if (tid == 0) {
        float s = 0.0f;
        #pragma unroll
        for (int i = 0; i < LAYERS; i++) s += gates[i];
        sG = s;
    }
    __syncthreads();

    const long long gt = (long long)blockIdx.x * TPB + tid;
    const long long f4base = gt * 2;
    if (f4base >= nfloat4) return;
    const bool have2 = (f4base + 1) < nfloat4;

    float4 a = x[f4base];                                   // rows 0,1: (x0,y0,x1,y1)
    float4 c = have2 ? x[f4base + 1] : make_float4(0,0,0,0); // rows 2,3

    // Row-pair state in packed f32x2:
    u64 Xa = pk2(a.x, a.z), Ya = pk2(a.y, a.w);   // rows 0,1  (exact f32 tanh)
    u64 Xc = pk2(c.x, c.z), Yc = pk2(c.y, c.w);   // rows 2,3  (f16x2 tanh)

    #pragma unroll 4
    for (int l = 0; l < LAYERS; l++) {
        const LayerP p = sP[l];

        // ---- pair A (rows 0,1): exact f32 tanh ----
        u64 argA0 = fma2(p.w00, Xa, fma2(p.w01, Ya, p.b0));
        u64 argA1 = fma2(p.w10, Xa, fma2(p.w11, Ya, p.b1));
        {
            float a0, a1, b0f, b1f;
            up2(a0, a1, argA0);
            up2(b0f, b1f, argA1);
            u64 tX = pk2(tanh_f32(a0), tanh_f32(a1));
            u64 tY = pk2(tanh_f32(b0f), tanh_f32(b1f));
            Xa = fma2(p.m, tX, Xa);
            Ya = fma2(p.m, tY, Ya);
        }

        // ---- pair C (rows 2,3): packed f16x2 tanh ----
        u64 argC0 = fma2(p.w00, Xc, fma2(p.w01, Yc, p.b0));
        u64 argC1 = fma2(p.w10, Xc, fma2(p.w11, Yc, p.b1));
        {
            float a0, a1, b0f, b1f;
            up2(a0, a1, argC0);
            up2(b0f, b1f, argC1);
            unsigned hX = tanh_h2(pack_h2(a1, a0));
            unsigned hY = tanh_h2(pack_h2(b1f, b0f));
            float tx0, tx1, ty0, ty1;
            unpack_h2(tx0, tx1, hX);
            unpack_h2(ty0, ty1, hY);
            Xc = fma2(p.m, pk2(tx0, tx1), Xc);
            Yc = fma2(p.m, pk2(ty0, ty1), Yc);
        }
    }

    const float g = sG;
    const u64 g2 = pk2(g, g);
    Xa = mul2(g2, Xa); Ya = mul2(g2, Ya);
    Xc = mul2(g2, Xc); Yc = mul2(g2, Yc);

    float x0, x1, y0, y1;
    up2(x0, x1, Xa); up2(y0, y1, Ya);
    out[f4base] = make_float4(x0, y0, x1, y1);
    if (have2) {
        up2(x0, x1, Xc); up2(y0, y1, Yc);
        out[f4base + 1] = make_float4(x0, y0, x1, y1);
    }
}

extern "C" void kernel_launch(void* const* d_in, const int* in_sizes, int n_in,
                              void* d_out, int out_size)
{
    const float4* x     = (const float4*)d_in[0];
    const float*  W     = (const float*) d_in[1];
    const float*  b     = (const float*) d_in[2];
    const float*  masks = (const float*) d_in[3];
    const float*  gates = (const float*) d_in[4];
    float4* out = (float4*)d_out;

    const long long nfloat  = (long long)in_sizes[0];   // BATCH * 2
    const long long nfloat4 = nfloat / 4;               // BATCH / 2
    const long long threads = (nfloat4 + 1) / 2;
    const int blocks = (int)((threads + TPB - 1) / TPB);
    rdb_kernel<<<blocks, TPB>>>(x, W, b, masks, gates, out, nfloat4);
}